// round 3
// baseline (speedup 1.0000x reference)
#include <cuda_runtime.h>
#include <cuda_bf16.h>
#include <cstdint>

// Problem constants
#define Bn   4
#define Sn   4096
#define Dn   1024
#define Hn   8
#define Mn   32
#define Wn   16
#define NSn  128
#define GHn  128
#define TEMP 0.6f
#define SIGMA 0.12f
#define ALPHA 6.0f

// ---------------- scratch (device globals; no allocations allowed) ----------------
__device__ float g_pool_part[32 * Bn * Dn];     // [schunk][b][d] partial sums
__device__ float g_weights[Hn * Bn * Mn];       // softmax gate weights
__device__ float g_final[Hn * Bn * Sn];         // final_grid
__device__ float g_dens[Hn * Bn * Sn];          // raw density (pre-normalization)
__device__ float g_densSum[Hn * Bn];            // per (h,b) sum over s

// ---------------- 1) pooled partial sums over S ----------------
// grid (Dn/256=4, 32, Bn=4), block 256
__global__ void pool_kernel(const float* __restrict__ x) {
    int d  = blockIdx.x * 256 + threadIdx.x;
    int sc = blockIdx.y;
    int b  = blockIdx.z;
    const float* xp = x + ((size_t)b * Sn + (size_t)sc * 128) * Dn + d;
    float acc = 0.f;
#pragma unroll 8
    for (int i = 0; i < 128; i++) acc += xp[(size_t)i * Dn];
    g_pool_part[(sc * Bn + b) * Dn + d] = acc;
}

// ---------------- 2) gating MLP -> softmax weights ----------------
// grid (Bn, Hn), block 128
__global__ void gate_kernel(const float* __restrict__ W1, const float* __restrict__ b1,
                            const float* __restrict__ W2, const float* __restrict__ b2) {
    int b = blockIdx.x, h = blockIdx.y, t = threadIdx.x;
    __shared__ float sp[Dn];
    __shared__ float sh[GHn];

    for (int i = t; i < Dn; i += 128) {
        float a = 0.f;
#pragma unroll
        for (int c = 0; c < 32; c++) a += g_pool_part[(c * Bn + b) * Dn + i];
        sp[i] = a * (1.0f / (float)Sn);
    }
    __syncthreads();

    // hpre[g] = relu(sum_d pooled[d] * W1[h,d,g] + b1[h,g])
    {
        float acc = b1[h * GHn + t];
        const float* w1 = W1 + (size_t)h * Dn * GHn + t;
#pragma unroll 4
        for (int d = 0; d < Dn; d++) acc = fmaf(sp[d], w1[(size_t)d * GHn], acc);
        sh[t] = fmaxf(acc, 0.0f);
    }
    __syncthreads();

    if (t < Mn) {
        float l = b2[h * Mn + t];
        const float* w2 = W2 + h * GHn * Mn + t;
#pragma unroll
        for (int g = 0; g < GHn; g++) l = fmaf(sh[g], w2[g * Mn], l);
        l *= (1.0f / TEMP);
        float mx = l;
        for (int o = 16; o; o >>= 1) mx = fmaxf(mx, __shfl_xor_sync(0xffffffffu, mx, o));
        float e = __expf(l - mx);
        float sm = e;
        for (int o = 16; o; o >>= 1) sm += __shfl_xor_sync(0xffffffffu, sm, o);
        g_weights[(h * Bn + b) * Mn + t] = e / sm;
    }
    if (t == 0) g_densSum[h * Bn + b] = 0.f;
}

// ---------------- 3) waves -> mask grids -> gated final_grid ----------------
// grid (Sn/128=32, Hn), block 128 (one thread per s)
__global__ void wave_kernel(const float* __restrict__ freqs, const float* __restrict__ amps,
                            const float* __restrict__ phases) {
    int h = blockIdx.y, t = threadIdx.x;
    int s = blockIdx.x * 128 + t;
    __shared__ float sf0[Mn * Wn], sf1[Mn * Wn], sc[Mn * Wn], sa[Mn * Wn];
    __shared__ float sw[Bn * Mn];

    for (int i = t; i < Mn * Wn; i += 128) {
        sf0[i] = freqs[(h * Mn * Wn + i) * 2 + 0];
        sf1[i] = freqs[(h * Mn * Wn + i) * 2 + 1];
        // triangle(2*pi*dot + ph): t = dot + (ph - pi/2)/(2*pi)
        sc[i] = (phases[h * Mn * Wn + i] - 1.5707963267948966f) * 0.15915494309189535f;
        sa[i] = amps[h * Mn * Wn + i];
    }
    sw[t] = g_weights[h * Bn * Mn + t];   // [b*32+m]
    __syncthreads();

    float px = -1.0f + (2.0f / 63.0f) * (float)(s & 63);
    float py = -1.0f + (2.0f / 63.0f) * (float)(s >> 6);

    float fg0 = 0.f, fg1 = 0.f, fg2 = 0.f, fg3 = 0.f;
    for (int m = 0; m < Mn; m++) {
        float acc = 0.f;
#pragma unroll
        for (int w = 0; w < Wn; w++) {
            int i = m * Wn + w;
            float tt = fmaf(px, sf0[i], fmaf(py, sf1[i], sc[i]));
            float fr = tt - floorf(tt);
            // wave = amp * (1 - 4*|frac-0.5|)
            acc = fmaf(sa[i], fmaf(-4.0f, fabsf(fr - 0.5f), 1.0f), acc);
        }
        fg0 = fmaf(sw[0 * Mn + m], acc, fg0);
        fg1 = fmaf(sw[1 * Mn + m], acc, fg1);
        fg2 = fmaf(sw[2 * Mn + m], acc, fg2);
        fg3 = fmaf(sw[3 * Mn + m], acc, fg3);
    }
    int base = h * Bn * Sn + s;
    g_final[base + 0 * Sn] = fg0;
    g_final[base + 1 * Sn] = fg1;
    g_final[base + 2 * Sn] = fg2;
    g_final[base + 3 * Sn] = fg3;
}

// ---------------- 4) MC density (mean of sigmoid over NS) + row sums ----------------
// grid (Sn/256=16, Bn, Hn), block 256
__global__ void density_kernel(const float* __restrict__ noise) {
    int s = blockIdx.x * 256 + threadIdx.x;
    int b = blockIdx.y, h = blockIdx.z;
    int hb = h * Bn + b;
    float zb = ALPHA * g_final[hb * Sn + s];
    const float* np_ = noise + (size_t)hb * NSn * Sn + s;
    float acc = 0.f;
#pragma unroll 4
    for (int ns = 0; ns < NSn; ns++) {
        float z = fmaf(ALPHA * SIGMA, np_[(size_t)ns * Sn], zb);
        acc += __fdividef(1.0f, 1.0f + __expf(-z));
    }
    float v = acc * (1.0f / (float)NSn);
    g_dens[hb * Sn + s] = v;

    // block-reduce v, accumulate into g_densSum[hb]
    float r = v;
    for (int o = 16; o; o >>= 1) r += __shfl_xor_sync(0xffffffffu, r, o);
    __shared__ float sred[8];
    if ((threadIdx.x & 31) == 0) sred[threadIdx.x >> 5] = r;
    __syncthreads();
    if (threadIdx.x < 8) {
        float rr = sred[threadIdx.x];
        for (int o = 4; o; o >>= 1) rr += __shfl_xor_sync(0xffu, rr, o);
        if (threadIdx.x == 0) atomicAdd(&g_densSum[hb], rr);
    }
}

// ---------------- 5) fused scale + bf16 mma GEMM + residual epilogue ----------------
// out[r,n] = sum_k (dens[h(k),b(r),s(r)]/(sum+1e-8) * x[r,k]) * Wo[k,n] + bo[n] + x[r,n]
// CTA tile 128x128, BK=32, 256 threads, 8 warps (2M x 4N), warp tile 64x32 via m16n8k16.
#define AST 40   // As row stride (bf16 elems): conflict-free for frag loads
#define BST 34   // Bs (B^T, [n][k]) row stride

#define MMA16816(C, A, Bf)                                                             \
    asm volatile("mma.sync.aligned.m16n8k16.row.col.f32.bf16.bf16.f32 "                \
                 "{%0,%1,%2,%3},{%4,%5,%6,%7},{%8,%9},{%0,%1,%2,%3};\n"                \
                 : "+f"(C[0]), "+f"(C[1]), "+f"(C[2]), "+f"(C[3])                      \
                 : "r"(A[0]), "r"(A[1]), "r"(A[2]), "r"(A[3]), "r"(Bf[0]), "r"(Bf[1]))

__global__ __launch_bounds__(256) void gemm_kernel(const float* __restrict__ x,
                                                   const float* __restrict__ Wo,
                                                   const float* __restrict__ bo,
                                                   float* __restrict__ out) {
    __shared__ __align__(16) __nv_bfloat16 As[2 * 128 * AST];
    __shared__ __align__(16) __nv_bfloat16 Bs[2 * 128 * BST];
    __shared__ float ssc[Hn * 128];

    const int tid = threadIdx.x;
    const int mb = blockIdx.y, nb = blockIdx.x;
    const int bidx = mb >> 5;              // 32 m-blocks per batch (4096/128)
    const int s0 = (mb & 31) * 128;

    // per-row per-head normalized density scales for this CTA's 128 rows
    for (int i = tid; i < Hn * 128; i += 256) {
        int h = i >> 7, r = i & 127;
        int hb = h * Bn + bidx;
        ssc[i] = g_dens[hb * Sn + s0 + r] / (g_densSum[hb] + 1e-8f);
    }

    const int warpId = tid >> 5, lane = tid & 31;
    const int wm = warpId & 1, wn = warpId >> 1;
    const int g = lane >> 2, t4 = lane & 3;

    const int arow = tid >> 3, acol = (tid & 7) * 4;   // A loader: 32 rows/pass x 8 f4
    const int brow = tid >> 5, bcol = lane * 4;        // B loader: 8 k-rows/pass x 128 cols

    const float* Abase = x + (size_t)(mb * 128) * Dn;
    float4 aR[4], bR[4];

    auto gld = [&](int kt) {
        int k0 = kt * 32;
#pragma unroll
        for (int p = 0; p < 4; p++)
            aR[p] = *(const float4*)(Abase + (size_t)(arow + p * 32) * Dn + k0 + acol);
#pragma unroll
        for (int p = 0; p < 4; p++)
            bR[p] = *(const float4*)(Wo + (size_t)(k0 + brow + p * 8) * Dn + nb * 128 + bcol);
    };

    auto sts = [&](int kt, int buf) {
        int h = kt >> 2;  // k0/128
        __nv_bfloat16* Ad = As + buf * (128 * AST);
#pragma unroll
        for (int p = 0; p < 4; p++) {
            int r = arow + p * 32;
            float sc = ssc[h * 128 + r];
            __nv_bfloat162 lo = __floats2bfloat162_rn(aR[p].x * sc, aR[p].y * sc);
            __nv_bfloat162 hi = __floats2bfloat162_rn(aR[p].z * sc, aR[p].w * sc);
            *(__nv_bfloat162*)(Ad + r * AST + acol) = lo;
            *(__nv_bfloat162*)(Ad + r * AST + acol + 2) = hi;
        }
        __nv_bfloat16* Bd = Bs + buf * (128 * BST);
#pragma unroll
        for (int p = 0; p < 4; p++) {
            int kk = brow + p * 8;
            Bd[(bcol + 0) * BST + kk] = __float2bfloat16(bR[p].x);
            Bd[(bcol + 1) * BST + kk] = __float2bfloat16(bR[p].y);
            Bd[(bcol + 2) * BST + kk] = __float2bfloat16(bR[p].z);
            Bd[(bcol + 3) * BST + kk] = __float2bfloat16(bR[p].w);
        }
    };

    gld(0);
    __syncthreads();   // ssc ready before sts uses it
    sts(0, 0);
    __syncthreads();

    float c_[4][4][4] = {};

    for (int kt = 0; kt < 32; kt++) {
        int buf = kt & 1;
        if (kt < 31) gld(kt + 1);

        const __nv_bfloat16* Ab = As + buf * (128 * AST);
        const __nv_bfloat16* Bb = Bs + buf * (128 * BST);
#pragma unroll
        for (int ks = 0; ks < 32; ks += 16) {
            uint32_t af[4][4], bfr[4][2];
#pragma unroll
            for (int mt = 0; mt < 4; mt++) {
                const __nv_bfloat16* ap = Ab + (wm * 64 + mt * 16 + g) * AST + ks + 2 * t4;
                af[mt][0] = *(const uint32_t*)(ap);
                af[mt][1] = *(const uint32_t*)(ap + 8 * AST);
                af[mt][2] = *(const uint32_t*)(ap + 8);
                af[mt][3] = *(const uint32_t*)(ap + 8 * AST + 8);
            }
#pragma unroll
            for (int nt = 0; nt < 4; nt++) {
                const __nv_bfloat16* bp = Bb + (wn * 32 + nt * 8 + g) * BST + ks + 2 * t4;
                bfr[nt][0] = *(const uint32_t*)(bp);
                bfr[nt][1] = *(const uint32_t*)(bp + 8);
            }
#pragma unroll
            for (int mt = 0; mt < 4; mt++)
#pragma unroll
                for (int nt = 0; nt < 4; nt++) MMA16816(c_[mt][nt], af[mt], bfr[nt]);
        }

        if (kt < 31) {
            sts(kt + 1, buf ^ 1);
            __syncthreads();
        }
    }

    // epilogue: + x + bo
#pragma unroll
    for (int mt = 0; mt < 4; mt++) {
        int r0 = mb * 128 + wm * 64 + mt * 16 + g;
#pragma unroll
        for (int nt = 0; nt < 4; nt++) {
            int cc = nb * 128 + wn * 32 + nt * 8 + 2 * t4;
            float2 bo2 = *(const float2*)(bo + cc);
            float2 x0 = *(const float2*)(x + (size_t)r0 * Dn + cc);
            float2 x1 = *(const float2*)(x + (size_t)(r0 + 8) * Dn + cc);
            float2 o0 = make_float2(c_[mt][nt][0] + x0.x + bo2.x, c_[mt][nt][1] + x0.y + bo2.y);
            float2 o1 = make_float2(c_[mt][nt][2] + x1.x + bo2.x, c_[mt][nt][3] + x1.y + bo2.y);
            *(float2*)(out + (size_t)r0 * Dn + cc) = o0;
            *(float2*)(out + (size_t)(r0 + 8) * Dn + cc) = o1;
        }
    }
}

// ---------------- launcher ----------------
extern "C" void kernel_launch(void* const* d_in, const int* in_sizes, int n_in,
                              void* d_out, int out_size) {
    const float* x      = (const float*)d_in[0];
    const float* noise  = (const float*)d_in[1];
    const float* W1     = (const float*)d_in[2];
    const float* b1     = (const float*)d_in[3];
    const float* W2     = (const float*)d_in[4];
    const float* b2     = (const float*)d_in[5];
    const float* freqs  = (const float*)d_in[6];
    const float* amps   = (const float*)d_in[7];
    const float* phases = (const float*)d_in[8];
    const float* Wo     = (const float*)d_in[9];
    const float* bo     = (const float*)d_in[10];
    float* out          = (float*)d_out;

    pool_kernel<<<dim3(Dn / 256, 32, Bn), 256>>>(x);
    gate_kernel<<<dim3(Bn, Hn), 128>>>(W1, b1, W2, b2);
    wave_kernel<<<dim3(Sn / 128, Hn), 128>>>(freqs, amps, phases);
    density_kernel<<<dim3(Sn / 256, Bn, Hn), 256>>>(noise);
    gemm_kernel<<<dim3(Dn / 128, (Bn * Sn) / 128), 256>>>(x, Wo, bo, out);
}

// round 6
// speedup vs baseline: 1.2561x; 1.2561x over previous
#include <cuda_runtime.h>
#include <cuda_bf16.h>
#include <cstdint>

// Problem constants
#define Bn   4
#define Sn   4096
#define Dn   1024
#define Hn   8
#define Mn   32
#define Wn   16
#define NSn  128
#define GHn  128
#define TEMP 0.6f
#define SIGMA 0.12f
#define ALPHA 6.0f
#define HBS  (Hn * Bn * Sn)

// ---------------- scratch (device globals; no allocations allowed) ----------------
__device__ float g_pool_part[32 * Bn * Dn];
__device__ float g_weights[Hn * Bn * Mn];
__device__ float g_final[HBS];
__device__ float g_densP[2 * HBS];          // two NS-halves of raw density
__device__ float g_densSum[Hn * Bn];
__device__ __align__(16) __nv_bfloat16 g_Abf[(size_t)Bn * Sn * Dn];  // 32 MB scaled x, bf16 row-major
__device__ __align__(16) __nv_bfloat16 g_Bt[(size_t)Dn * Dn];        // 2 MB Wo^T [n][k] bf16

// ---------------- PTX helpers (compute_100-safe: cp.async + ldmatrix + mma.sync) ----
__device__ __forceinline__ uint32_t smem_u32(const void* p) {
    uint32_t a;
    asm("{ .reg .u64 t; cvta.to.shared.u64 t, %1; cvt.u32.u64 %0, t; }" : "=r"(a) : "l"(p));
    return a;
}
#define CP16(dst, src) \
    asm volatile("cp.async.cg.shared.global [%0], [%1], 16;" :: "r"(dst), "l"(src))
#define CP_COMMIT() asm volatile("cp.async.commit_group;" ::: "memory")
#define CP_WAIT(n)  asm volatile("cp.async.wait_group %0;" :: "n"(n) : "memory")

#define LDSM4(r0, r1, r2, r3, addr)                                              \
    asm volatile("ldmatrix.sync.aligned.m8n8.x4.shared.b16 {%0,%1,%2,%3}, [%4];" \
                 : "=r"(r0), "=r"(r1), "=r"(r2), "=r"(r3) : "r"(addr))

#define MMA16816(C, A, Bf)                                                      \
    asm volatile("mma.sync.aligned.m16n8k16.row.col.f32.bf16.bf16.f32 "         \
                 "{%0,%1,%2,%3},{%4,%5,%6,%7},{%8,%9},{%0,%1,%2,%3};\n"         \
                 : "+f"(C[0]), "+f"(C[1]), "+f"(C[2]), "+f"(C[3])               \
                 : "r"(A[0]), "r"(A[1]), "r"(A[2]), "r"(A[3]),                  \
                   "r"(Bf[0]), "r"(Bf[1]))

// ---------------- 1) pooled partial sums over S ----------------
__global__ void pool_kernel(const float* __restrict__ x) {
    int d  = blockIdx.x * 256 + threadIdx.x;
    int sc = blockIdx.y;
    int b  = blockIdx.z;
    const float* xp = x + ((size_t)b * Sn + (size_t)sc * 128) * Dn + d;
    float a0 = 0.f, a1 = 0.f;
#pragma unroll 8
    for (int i = 0; i < 128; i += 2) {
        a0 += xp[(size_t)i * Dn];
        a1 += xp[(size_t)(i + 1) * Dn];
    }
    g_pool_part[(sc * Bn + b) * Dn + d] = a0 + a1;
}

// ---------------- 2) gating MLP -> softmax weights ----------------
__global__ void gate_kernel(const float* __restrict__ W1, const float* __restrict__ b1,
                            const float* __restrict__ W2, const float* __restrict__ b2) {
    int b = blockIdx.x, h = blockIdx.y, t = threadIdx.x;
    __shared__ float sp[Dn];
    __shared__ float sh[GHn];

    for (int i = t; i < Dn; i += 128) {
        float a = 0.f;
#pragma unroll
        for (int c = 0; c < 32; c++) a += g_pool_part[(c * Bn + b) * Dn + i];
        sp[i] = a * (1.0f / (float)Sn);
    }
    __syncthreads();
    {
        float acc = b1[h * GHn + t];
        const float* w1 = W1 + (size_t)h * Dn * GHn + t;
#pragma unroll 4
        for (int d = 0; d < Dn; d++) acc = fmaf(sp[d], w1[(size_t)d * GHn], acc);
        sh[t] = fmaxf(acc, 0.0f);
    }
    __syncthreads();
    if (t < Mn) {
        float l = b2[h * Mn + t];
        const float* w2 = W2 + h * GHn * Mn + t;
#pragma unroll
        for (int g = 0; g < GHn; g++) l = fmaf(sh[g], w2[g * Mn], l);
        l *= (1.0f / TEMP);
        float mx = l;
        for (int o = 16; o; o >>= 1) mx = fmaxf(mx, __shfl_xor_sync(0xffffffffu, mx, o));
        float e = __expf(l - mx);
        float sm = e;
        for (int o = 16; o; o >>= 1) sm += __shfl_xor_sync(0xffffffffu, sm, o);
        g_weights[(h * Bn + b) * Mn + t] = e / sm;
    }
    if (t == 0) g_densSum[h * Bn + b] = 0.f;
}

// ---------------- 3) waves -> gated final_grid ----------------
__global__ void wave_kernel(const float* __restrict__ freqs, const float* __restrict__ amps,
                            const float* __restrict__ phases) {
    int h = blockIdx.y, t = threadIdx.x;
    int s = blockIdx.x * 128 + t;
    __shared__ float sf0[Mn * Wn], sf1[Mn * Wn], sc[Mn * Wn], sa[Mn * Wn];
    __shared__ float sw[Bn * Mn];

    for (int i = t; i < Mn * Wn; i += 128) {
        sf0[i] = freqs[(h * Mn * Wn + i) * 2 + 0];
        sf1[i] = freqs[(h * Mn * Wn + i) * 2 + 1];
        sc[i] = (phases[h * Mn * Wn + i] - 1.5707963267948966f) * 0.15915494309189535f;
        sa[i] = amps[h * Mn * Wn + i];
    }
    sw[t] = g_weights[h * Bn * Mn + t];
    __syncthreads();

    float px = -1.0f + (2.0f / 63.0f) * (float)(s & 63);
    float py = -1.0f + (2.0f / 63.0f) * (float)(s >> 6);

    float fg0 = 0.f, fg1 = 0.f, fg2 = 0.f, fg3 = 0.f;
    for (int m = 0; m < Mn; m++) {
        float acc = 0.f;
#pragma unroll
        for (int w = 0; w < Wn; w++) {
            int i = m * Wn + w;
            float tt = fmaf(px, sf0[i], fmaf(py, sf1[i], sc[i]));
            float fr = tt - floorf(tt);
            acc = fmaf(sa[i], fmaf(-4.0f, fabsf(fr - 0.5f), 1.0f), acc);
        }
        fg0 = fmaf(sw[0 * Mn + m], acc, fg0);
        fg1 = fmaf(sw[1 * Mn + m], acc, fg1);
        fg2 = fmaf(sw[2 * Mn + m], acc, fg2);
        fg3 = fmaf(sw[3 * Mn + m], acc, fg3);
    }
    int base = h * Bn * Sn + s;
    g_final[base + 0 * Sn] = fg0;
    g_final[base + 1 * Sn] = fg1;
    g_final[base + 2 * Sn] = fg2;
    g_final[base + 3 * Sn] = fg3;
}

// ---------------- 4) MC density (split NS across 2 block sets for occupancy) ------
// grid (Sn/256, Bn, Hn*2), block 256
__global__ void density_kernel(const float* __restrict__ noise) {
    int s = blockIdx.x * 256 + threadIdx.x;
    int b = blockIdx.y;
    int h = blockIdx.z >> 1, half = blockIdx.z & 1;
    int hb = h * Bn + b;
    float zb = ALPHA * g_final[hb * Sn + s];
    const float* np_ = noise + ((size_t)hb * NSn + half * 64) * Sn + s;
    float acc = 0.f;
#pragma unroll 16
    for (int ns = 0; ns < 64; ns++) {
        float z = fmaf(ALPHA * SIGMA, np_[(size_t)ns * Sn], zb);
        acc += __fdividef(1.0f, 1.0f + __expf(-z));
    }
    float v = acc * (1.0f / (float)NSn);   // half-sum scaled by full 1/NS
    g_densP[half * HBS + hb * Sn + s] = v;

    float r = v;
    for (int o = 16; o; o >>= 1) r += __shfl_xor_sync(0xffffffffu, r, o);
    __shared__ float sred[8];
    if ((threadIdx.x & 31) == 0) sred[threadIdx.x >> 5] = r;
    __syncthreads();
    if (threadIdx.x < 8) {
        float rr = sred[threadIdx.x];
        for (int o = 4; o; o >>= 1) rr += __shfl_xor_sync(0xffu, rr, o);
        if (threadIdx.x == 0) atomicAdd(&g_densSum[hb], rr);
    }
}

// ---------------- 5a) prep A: density-scaled x -> bf16 row-major ----------------
// grid 8192, block 256 (2 rows per block, 8 cols per thread)
__global__ void prepA_kernel(const float* __restrict__ x) {
    int t = threadIdx.x;
    int R = blockIdx.x * 2 + (t >> 7);
    int c0 = (t & 127) * 8;
    int b = R >> 12, s = R & 4095, h = c0 >> 7;
    int hb = h * Bn + b;
    float sc = (g_densP[hb * Sn + s] + g_densP[HBS + hb * Sn + s]) /
               (g_densSum[hb] + 1e-8f);

    const float4* src = (const float4*)(x + (size_t)R * Dn + c0);
    float4 v0 = src[0], v1 = src[1];
    __nv_bfloat162 p0 = __floats2bfloat162_rn(v0.x * sc, v0.y * sc);
    __nv_bfloat162 p1 = __floats2bfloat162_rn(v0.z * sc, v0.w * sc);
    __nv_bfloat162 p2 = __floats2bfloat162_rn(v1.x * sc, v1.y * sc);
    __nv_bfloat162 p3 = __floats2bfloat162_rn(v1.z * sc, v1.w * sc);
    uint4 o;
    o.x = *(uint32_t*)&p0; o.y = *(uint32_t*)&p1;
    o.z = *(uint32_t*)&p2; o.w = *(uint32_t*)&p3;
    *(uint4*)(g_Abf + (size_t)R * Dn + c0) = o;
}

// ---------------- 5b) prep B: transpose Wo -> bf16 [n][k] ----------------
// grid (32, 32), block 256
__global__ void prepB_kernel(const float* __restrict__ Wo) {
    __shared__ float tile[32][33];
    int k0 = blockIdx.x * 32, n0 = blockIdx.y * 32;
    int c = threadIdx.x & 31, r0 = threadIdx.x >> 5;
#pragma unroll
    for (int i = 0; i < 4; i++)
        tile[r0 + 8 * i][c] = Wo[(size_t)(k0 + r0 + 8 * i) * Dn + n0 + c];
    __syncthreads();
    int c2 = (threadIdx.x & 15) * 2, r = threadIdx.x >> 4;
#pragma unroll
    for (int i = 0; i < 2; i++) {
        int rr = r + 16 * i;
        __nv_bfloat162 p = __floats2bfloat162_rn(tile[c2][rr], tile[c2 + 1][rr]);
        *(__nv_bfloat162*)(g_Bt + (size_t)(n0 + rr) * Dn + k0 + c2) = p;
    }
}

// ---------------- 5c) HMMA GEMM: out = (dens*x) @ Wo + x + bo ----------------
// CTA 128x128, BK=64, 4-stage cp.async pipeline, 256 thr, 8 warps (2m x 4n),
// warp tile 64x32, m16n8k16, ldmatrix.x4, xor-swizzled smem.
#define NSTG 4
#define NKT  16
#define STAGE_BYTES 32768        // A 16KB + B 16KB
#define GEMM_SMEM   (NSTG * STAGE_BYTES)

__global__ __launch_bounds__(256) void gemm_kernel(const float* __restrict__ x,
                                                   const float* __restrict__ bo,
                                                   float* __restrict__ out) {
    extern __shared__ __align__(16) uint8_t dsm[];
    const uint32_t tiles = smem_u32(dsm);

    const int tid = threadIdx.x;
    const int nb = blockIdx.x, mb = blockIdx.y;
    const int warpId = tid >> 5, lane = tid & 31;
    const int wm = warpId & 1, wn = warpId >> 1;
    const int g = lane >> 2, t4 = lane & 3;

    // loader mapping: 4 rows-of-32 per thread, 16B chunk per row
    const int arow = tid >> 3, acol = tid & 7;
    const __nv_bfloat16* Agp = g_Abf + (size_t)(mb * 128 + arow) * Dn + acol * 8;
    const __nv_bfloat16* Bgp = g_Bt + (size_t)(nb * 128 + arow) * Dn + acol * 8;

    auto issue = [&](int kt, int st) {
        uint32_t dA = tiles + st * STAGE_BYTES;
        uint32_t dB = dA + 16384;
        int k0 = kt * 64;
#pragma unroll
        for (int p = 0; p < 4; p++) {
            int row = arow + p * 32;
            uint32_t off = row * 128 + ((acol ^ (row & 7)) << 4);
            CP16(dA + off, Agp + (size_t)p * 32 * Dn + k0);
            CP16(dB + off, Bgp + (size_t)p * 32 * Dn + k0);
        }
        CP_COMMIT();
    };

    // ldmatrix per-lane address components (fixed across k)
    int amRow[4], amRB[4], amRK[4];
#pragma unroll
    for (int mt = 0; mt < 4; mt++) {
        amRow[mt] = wm * 64 + mt * 16 + (lane & 15);
        amRB[mt] = amRow[mt] * 128;
        amRK[mt] = amRow[mt] & 7;
    }
    const int ahi = lane >> 4;                           // A k-chunk high bit
    int bnRow[2], bnRB[2], bnRK[2];
    const int nidx = (lane & 7) | ((lane >> 1) & 8);
#pragma unroll
    for (int nt2 = 0; nt2 < 2; nt2++) {
        bnRow[nt2] = wn * 32 + nt2 * 16 + nidx;
        bnRB[nt2] = bnRow[nt2] * 128;
        bnRK[nt2] = bnRow[nt2] & 7;
    }
    const int bhi = (lane >> 3) & 1;                     // B k-chunk high bit

    float c_[4][4][4] = {};

    issue(0, 0);
    issue(1, 1);
    issue(2, 2);

    for (int kt = 0; kt < NKT; kt++) {
        CP_WAIT(2);
        __syncthreads();

        uint32_t aB = tiles + (kt & 3) * STAGE_BYTES;
        uint32_t bB = aB + 16384;

#pragma unroll
        for (int ks = 0; ks < 4; ks++) {
            uint32_t af[4][4], bf[2][4];
            const int cca = 2 * ks + ahi;
            const int ccb = 2 * ks + bhi;
#pragma unroll
            for (int mt = 0; mt < 4; mt++)
                LDSM4(af[mt][0], af[mt][1], af[mt][2], af[mt][3],
                      aB + amRB[mt] + ((cca ^ amRK[mt]) << 4));
#pragma unroll
            for (int nt2 = 0; nt2 < 2; nt2++)
                LDSM4(bf[nt2][0], bf[nt2][1], bf[nt2][2], bf[nt2][3],
                      bB + bnRB[nt2] + ((ccb ^ bnRK[nt2]) << 4));
#pragma unroll
            for (int mt = 0; mt < 4; mt++)
#pragma unroll
                for (int nt = 0; nt < 4; nt++) {
                    uint32_t bb[2] = {bf[nt >> 1][(nt & 1) * 2],
                                      bf[nt >> 1][(nt & 1) * 2 + 1]};
                    MMA16816(c_[mt][nt], af[mt], bb);
                }
        }

        __syncthreads();
        if (kt + 3 < NKT) issue(kt + 3, (kt + 3) & 3);
    }

    // epilogue: + x + bo
#pragma unroll
    for (int mt = 0; mt < 4; mt++) {
        int r0 = mb * 128 + wm * 64 + mt * 16 + g;
#pragma unroll
        for (int nt = 0; nt < 4; nt++) {
            int cc = nb * 128 + wn * 32 + nt * 8 + 2 * t4;
            float2 bo2 = *(const float2*)(bo + cc);
            float2 x0 = *(const float2*)(x + (size_t)r0 * Dn + cc);
            float2 x1 = *(const float2*)(x + (size_t)(r0 + 8) * Dn + cc);
            float2 o0 = make_float2(c_[mt][nt][0] + x0.x + bo2.x,
                                    c_[mt][nt][1] + x0.y + bo2.y);
            float2 o1 = make_float2(c_[mt][nt][2] + x1.x + bo2.x,
                                    c_[mt][nt][3] + x1.y + bo2.y);
            *(float2*)(out + (size_t)r0 * Dn + cc) = o0;
            *(float2*)(out + (size_t)(r0 + 8) * Dn + cc) = o1;
        }
    }
}

// ---------------- launcher ----------------
extern "C" void kernel_launch(void* const* d_in, const int* in_sizes, int n_in,
                              void* d_out, int out_size) {
    const float* x      = (const float*)d_in[0];
    const float* noise  = (const float*)d_in[1];
    const float* W1     = (const float*)d_in[2];
    const float* b1     = (const float*)d_in[3];
    const float* W2     = (const float*)d_in[4];
    const float* b2     = (const float*)d_in[5];
    const float* freqs  = (const float*)d_in[6];
    const float* amps   = (const float*)d_in[7];
    const float* phases = (const float*)d_in[8];
    const float* Wo     = (const float*)d_in[9];
    const float* bo     = (const float*)d_in[10];
    float* out          = (float*)d_out;

    // idempotent, capture-safe; called unconditionally (no static guards allowed)
    cudaFuncSetAttribute(gemm_kernel, cudaFuncAttributeMaxDynamicSharedMemorySize,
                         GEMM_SMEM);

    pool_kernel<<<dim3(Dn / 256, 32, Bn), 256>>>(x);
    gate_kernel<<<dim3(Bn, Hn), 128>>>(W1, b1, W2, b2);
    wave_kernel<<<dim3(Sn / 128, Hn), 128>>>(freqs, amps, phases);
    prepB_kernel<<<dim3(32, 32), 256>>>(Wo);
    density_kernel<<<dim3(Sn / 256, Bn, Hn * 2), 256>>>(noise);
    prepA_kernel<<<8192, 256>>>(x);
    gemm_kernel<<<dim3(Dn / 128, (Bn * Sn) / 128), 256, GEMM_SMEM>>>(x, bo, out);
}

// round 7
// speedup vs baseline: 1.4071x; 1.1203x over previous
#include <cuda_runtime.h>
#include <cuda_bf16.h>
#include <cstdint>

// Problem constants
#define Bn   4
#define Sn   4096
#define Dn   1024
#define Hn   8
#define Mn   32
#define Wn   16
#define NSn  128
#define GHn  128
#define TEMP 0.6f
#define SIGMA 0.12f
#define ALPHA 6.0f
#define HBS  (Hn * Bn * Sn)

// ---------------- scratch (device globals; no allocations allowed) ----------------
__device__ float g_pool_part[32 * Bn * Dn];
__device__ float g_weights[Hn * Bn * Mn];
__device__ float g_final[HBS];
__device__ float g_densP[2 * HBS];          // two NS-halves of raw density
__device__ float g_densSum[Hn * Bn];
__device__ __align__(16) __nv_bfloat16 g_Abf[(size_t)Bn * Sn * Dn];  // 32 MB scaled x, bf16 row-major
__device__ __align__(16) __nv_bfloat16 g_Bt[(size_t)Dn * Dn];        // 2 MB Wo^T [n][k] bf16

// ---------------- PTX helpers (compute_100-safe: cp.async + ldmatrix + mma.sync) ----
__device__ __forceinline__ uint32_t smem_u32(const void* p) {
    uint32_t a;
    asm("{ .reg .u64 t; cvta.to.shared.u64 t, %1; cvt.u32.u64 %0, t; }" : "=r"(a) : "l"(p));
    return a;
}
#define CP16(dst, src) \
    asm volatile("cp.async.cg.shared.global [%0], [%1], 16;" :: "r"(dst), "l"(src))
#define CP_COMMIT() asm volatile("cp.async.commit_group;" ::: "memory")
#define CP_WAIT(n)  asm volatile("cp.async.wait_group %0;" :: "n"(n) : "memory")

#define LDSM4(r0, r1, r2, r3, addr)                                              \
    asm volatile("ldmatrix.sync.aligned.m8n8.x4.shared.b16 {%0,%1,%2,%3}, [%4];" \
                 : "=r"(r0), "=r"(r1), "=r"(r2), "=r"(r3) : "r"(addr))

#define MMA16816(C, A, Bf)                                                      \
    asm volatile("mma.sync.aligned.m16n8k16.row.col.f32.bf16.bf16.f32 "         \
                 "{%0,%1,%2,%3},{%4,%5,%6,%7},{%8,%9},{%0,%1,%2,%3};\n"         \
                 : "+f"(C[0]), "+f"(C[1]), "+f"(C[2]), "+f"(C[3])               \
                 : "r"(A[0]), "r"(A[1]), "r"(A[2]), "r"(A[3]),                  \
                   "r"(Bf[0]), "r"(Bf[1]))

// ---------------- 1) pooled partial sums over S ----------------
__global__ void pool_kernel(const float* __restrict__ x) {
    int d  = blockIdx.x * 256 + threadIdx.x;
    int sc = blockIdx.y;
    int b  = blockIdx.z;
    const float* xp = x + ((size_t)b * Sn + (size_t)sc * 128) * Dn + d;
    float a0 = 0.f, a1 = 0.f;
#pragma unroll 8
    for (int i = 0; i < 128; i += 2) {
        a0 += xp[(size_t)i * Dn];
        a1 += xp[(size_t)(i + 1) * Dn];
    }
    g_pool_part[(sc * Bn + b) * Dn + d] = a0 + a1;
}

// ---------------- 2) gating MLP -> softmax weights ----------------
__global__ void gate_kernel(const float* __restrict__ W1, const float* __restrict__ b1,
                            const float* __restrict__ W2, const float* __restrict__ b2) {
    int b = blockIdx.x, h = blockIdx.y, t = threadIdx.x;
    __shared__ float sp[Dn];
    __shared__ float sh[GHn];

    for (int i = t; i < Dn; i += 128) {
        float a = 0.f;
#pragma unroll
        for (int c = 0; c < 32; c++) a += g_pool_part[(c * Bn + b) * Dn + i];
        sp[i] = a * (1.0f / (float)Sn);
    }
    __syncthreads();
    {
        float acc = b1[h * GHn + t];
        const float* w1 = W1 + (size_t)h * Dn * GHn + t;
#pragma unroll 4
        for (int d = 0; d < Dn; d++) acc = fmaf(sp[d], w1[(size_t)d * GHn], acc);
        sh[t] = fmaxf(acc, 0.0f);
    }
    __syncthreads();
    if (t < Mn) {
        float l = b2[h * Mn + t];
        const float* w2 = W2 + h * GHn * Mn + t;
#pragma unroll
        for (int g = 0; g < GHn; g++) l = fmaf(sh[g], w2[g * Mn], l);
        l *= (1.0f / TEMP);
        float mx = l;
        for (int o = 16; o; o >>= 1) mx = fmaxf(mx, __shfl_xor_sync(0xffffffffu, mx, o));
        float e = __expf(l - mx);
        float sm = e;
        for (int o = 16; o; o >>= 1) sm += __shfl_xor_sync(0xffffffffu, sm, o);
        g_weights[(h * Bn + b) * Mn + t] = e / sm;
    }
    if (t == 0) g_densSum[h * Bn + b] = 0.f;
}

// ---------------- 3) waves -> gated final_grid ----------------
__global__ void wave_kernel(const float* __restrict__ freqs, const float* __restrict__ amps,
                            const float* __restrict__ phases) {
    int h = blockIdx.y, t = threadIdx.x;
    int s = blockIdx.x * 128 + t;
    __shared__ float sf0[Mn * Wn], sf1[Mn * Wn], sc[Mn * Wn], sa[Mn * Wn];
    __shared__ float sw[Bn * Mn];

    for (int i = t; i < Mn * Wn; i += 128) {
        sf0[i] = freqs[(h * Mn * Wn + i) * 2 + 0];
        sf1[i] = freqs[(h * Mn * Wn + i) * 2 + 1];
        sc[i] = (phases[h * Mn * Wn + i] - 1.5707963267948966f) * 0.15915494309189535f;
        sa[i] = amps[h * Mn * Wn + i];
    }
    sw[t] = g_weights[h * Bn * Mn + t];
    __syncthreads();

    float px = -1.0f + (2.0f / 63.0f) * (float)(s & 63);
    float py = -1.0f + (2.0f / 63.0f) * (float)(s >> 6);

    float fg0 = 0.f, fg1 = 0.f, fg2 = 0.f, fg3 = 0.f;
    for (int m = 0; m < Mn; m++) {
        float acc = 0.f;
#pragma unroll
        for (int w = 0; w < Wn; w++) {
            int i = m * Wn + w;
            float tt = fmaf(px, sf0[i], fmaf(py, sf1[i], sc[i]));
            float fr = tt - floorf(tt);
            acc = fmaf(sa[i], fmaf(-4.0f, fabsf(fr - 0.5f), 1.0f), acc);
        }
        fg0 = fmaf(sw[0 * Mn + m], acc, fg0);
        fg1 = fmaf(sw[1 * Mn + m], acc, fg1);
        fg2 = fmaf(sw[2 * Mn + m], acc, fg2);
        fg3 = fmaf(sw[3 * Mn + m], acc, fg3);
    }
    int base = h * Bn * Sn + s;
    g_final[base + 0 * Sn] = fg0;
    g_final[base + 1 * Sn] = fg1;
    g_final[base + 2 * Sn] = fg2;
    g_final[base + 3 * Sn] = fg3;
}

// ---------------- 4) MC density (split NS across 2 block sets for occupancy) ------
// grid (Sn/256, Bn, Hn*2), block 256
__global__ void density_kernel(const float* __restrict__ noise) {
    int s = blockIdx.x * 256 + threadIdx.x;
    int b = blockIdx.y;
    int h = blockIdx.z >> 1, half = blockIdx.z & 1;
    int hb = h * Bn + b;
    float zb = ALPHA * g_final[hb * Sn + s];
    const float* np_ = noise + ((size_t)hb * NSn + half * 64) * Sn + s;
    float acc = 0.f;
#pragma unroll 16
    for (int ns = 0; ns < 64; ns++) {
        float z = fmaf(ALPHA * SIGMA, np_[(size_t)ns * Sn], zb);
        acc += __fdividef(1.0f, 1.0f + __expf(-z));
    }
    float v = acc * (1.0f / (float)NSn);   // half-sum scaled by full 1/NS
    g_densP[half * HBS + hb * Sn + s] = v;

    float r = v;
    for (int o = 16; o; o >>= 1) r += __shfl_xor_sync(0xffffffffu, r, o);
    __shared__ float sred[8];
    if ((threadIdx.x & 31) == 0) sred[threadIdx.x >> 5] = r;
    __syncthreads();
    if (threadIdx.x < 8) {
        float rr = sred[threadIdx.x];
        for (int o = 4; o; o >>= 1) rr += __shfl_xor_sync(0xffu, rr, o);
        if (threadIdx.x == 0) atomicAdd(&g_densSum[hb], rr);
    }
}

// ---------------- 5a) prep A: density-scaled x -> bf16 row-major ----------------
// grid 8192, block 256 (2 rows per block, 8 cols per thread)
__global__ void prepA_kernel(const float* __restrict__ x) {
    int t = threadIdx.x;
    int R = blockIdx.x * 2 + (t >> 7);
    int c0 = (t & 127) * 8;
    int b = R >> 12, s = R & 4095, h = c0 >> 7;
    int hb = h * Bn + b;
    float sc = (g_densP[hb * Sn + s] + g_densP[HBS + hb * Sn + s]) /
               (g_densSum[hb] + 1e-8f);

    const float4* src = (const float4*)(x + (size_t)R * Dn + c0);
    float4 v0 = src[0], v1 = src[1];
    __nv_bfloat162 p0 = __floats2bfloat162_rn(v0.x * sc, v0.y * sc);
    __nv_bfloat162 p1 = __floats2bfloat162_rn(v0.z * sc, v0.w * sc);
    __nv_bfloat162 p2 = __floats2bfloat162_rn(v1.x * sc, v1.y * sc);
    __nv_bfloat162 p3 = __floats2bfloat162_rn(v1.z * sc, v1.w * sc);
    uint4 o;
    o.x = *(uint32_t*)&p0; o.y = *(uint32_t*)&p1;
    o.z = *(uint32_t*)&p2; o.w = *(uint32_t*)&p3;
    *(uint4*)(g_Abf + (size_t)R * Dn + c0) = o;
}

// ---------------- 5b) prep B: transpose Wo -> bf16 [n][k] ----------------
// grid (32, 32), block 256
__global__ void prepB_kernel(const float* __restrict__ Wo) {
    __shared__ float tile[32][33];
    int k0 = blockIdx.x * 32, n0 = blockIdx.y * 32;
    int c = threadIdx.x & 31, r0 = threadIdx.x >> 5;
#pragma unroll
    for (int i = 0; i < 4; i++)
        tile[r0 + 8 * i][c] = Wo[(size_t)(k0 + r0 + 8 * i) * Dn + n0 + c];
    __syncthreads();
    int c2 = (threadIdx.x & 15) * 2, r = threadIdx.x >> 4;
#pragma unroll
    for (int i = 0; i < 2; i++) {
        int rr = r + 16 * i;
        __nv_bfloat162 p = __floats2bfloat162_rn(tile[c2][rr], tile[c2 + 1][rr]);
        *(__nv_bfloat162*)(g_Bt + (size_t)(n0 + rr) * Dn + k0 + c2) = p;
    }
}

// ---------------- 5c) HMMA GEMM: out = (dens*x) @ Wo + x + bo ----------------
// CTA 128x128, BK=64, 3-stage cp.async pipeline (96KB -> 2 CTAs/SM), 256 thr,
// 8 warps (2m x 4n), warp tile 64x32, m16n8k16, ldmatrix.x4, xor-swizzled smem.
// ONE __syncthreads per k-tile: the load issued after the barrier targets the
// stage consumed in iteration kt-1, which all warps have finished by then.
#define NSTG 3
#define NKT  16
#define STAGE_BYTES 32768        // A 16KB + B 16KB
#define GEMM_SMEM   (NSTG * STAGE_BYTES)

__global__ __launch_bounds__(256, 2) void gemm_kernel(const float* __restrict__ x,
                                                      const float* __restrict__ bo,
                                                      float* __restrict__ out) {
    extern __shared__ __align__(16) uint8_t dsm[];
    const uint32_t tiles = smem_u32(dsm);

    const int tid = threadIdx.x;
    const int nb = blockIdx.x, mb = blockIdx.y;
    const int warpId = tid >> 5, lane = tid & 31;
    const int wm = warpId & 1, wn = warpId >> 1;
    const int g = lane >> 2, t4 = lane & 3;

    // loader mapping: 4 rows-of-32 per thread, 16B chunk per row
    const int arow = tid >> 3, acol = tid & 7;
    const __nv_bfloat16* Agp = g_Abf + (size_t)(mb * 128 + arow) * Dn + acol * 8;
    const __nv_bfloat16* Bgp = g_Bt + (size_t)(nb * 128 + arow) * Dn + acol * 8;

    auto issue = [&](int kt, int st) {
        uint32_t dA = tiles + st * STAGE_BYTES;
        uint32_t dB = dA + 16384;
        int k0 = kt * 64;
#pragma unroll
        for (int p = 0; p < 4; p++) {
            int row = arow + p * 32;
            uint32_t off = row * 128 + ((acol ^ (row & 7)) << 4);
            CP16(dA + off, Agp + (size_t)p * 32 * Dn + k0);
            CP16(dB + off, Bgp + (size_t)p * 32 * Dn + k0);
        }
        CP_COMMIT();
    };

    // ldmatrix per-lane address components (fixed across k)
    int amRB[4], amRK[4];
#pragma unroll
    for (int mt = 0; mt < 4; mt++) {
        int amRow = wm * 64 + mt * 16 + (lane & 15);
        amRB[mt] = amRow * 128;
        amRK[mt] = amRow & 7;
    }
    const int ahi = lane >> 4;                           // A k-chunk high bit
    int bnRB[2], bnRK[2];
    const int nidx = (lane & 7) | ((lane >> 1) & 8);
#pragma unroll
    for (int nt2 = 0; nt2 < 2; nt2++) {
        int bnRow = wn * 32 + nt2 * 16 + nidx;
        bnRB[nt2] = bnRow * 128;
        bnRK[nt2] = bnRow & 7;
    }
    const int bhi = (lane >> 3) & 1;                     // B k-chunk high bit

    float c_[4][4][4] = {};

    issue(0, 0);
    issue(1, 1);

    int st = 0;
    for (int kt = 0; kt < NKT; kt++) {
        CP_WAIT(1);
        __syncthreads();

        // prefetch kt+2 into the stage consumed at kt-1 (safe: all warps past barrier)
        if (kt + 2 < NKT) {
            int stNext = st + 2;
            if (stNext >= NSTG) stNext -= NSTG;
            issue(kt + 2, stNext);
        }

        uint32_t aB = tiles + st * STAGE_BYTES;
        uint32_t bB = aB + 16384;

#pragma unroll
        for (int ks = 0; ks < 4; ks++) {
            uint32_t af[4][4], bf[2][4];
            const int cca = 2 * ks + ahi;
            const int ccb = 2 * ks + bhi;
#pragma unroll
            for (int mt = 0; mt < 4; mt++)
                LDSM4(af[mt][0], af[mt][1], af[mt][2], af[mt][3],
                      aB + amRB[mt] + ((cca ^ amRK[mt]) << 4));
#pragma unroll
            for (int nt2 = 0; nt2 < 2; nt2++)
                LDSM4(bf[nt2][0], bf[nt2][1], bf[nt2][2], bf[nt2][3],
                      bB + bnRB[nt2] + ((ccb ^ bnRK[nt2]) << 4));
#pragma unroll
            for (int mt = 0; mt < 4; mt++)
#pragma unroll
                for (int nt = 0; nt < 4; nt++) {
                    uint32_t bb[2] = {bf[nt >> 1][(nt & 1) * 2],
                                      bf[nt >> 1][(nt & 1) * 2 + 1]};
                    MMA16816(c_[mt][nt], af[mt], bb);
                }
        }

        if (++st == NSTG) st = 0;
    }

    // epilogue: + x + bo
#pragma unroll
    for (int mt = 0; mt < 4; mt++) {
        int r0 = mb * 128 + wm * 64 + mt * 16 + g;
#pragma unroll
        for (int nt = 0; nt < 4; nt++) {
            int cc = nb * 128 + wn * 32 + nt * 8 + 2 * t4;
            float2 bo2 = *(const float2*)(bo + cc);
            float2 x0 = *(const float2*)(x + (size_t)r0 * Dn + cc);
            float2 x1 = *(const float2*)(x + (size_t)(r0 + 8) * Dn + cc);
            float2 o0 = make_float2(c_[mt][nt][0] + x0.x + bo2.x,
                                    c_[mt][nt][1] + x0.y + bo2.y);
            float2 o1 = make_float2(c_[mt][nt][2] + x1.x + bo2.x,
                                    c_[mt][nt][3] + x1.y + bo2.y);
            *(float2*)(out + (size_t)r0 * Dn + cc) = o0;
            *(float2*)(out + (size_t)(r0 + 8) * Dn + cc) = o1;
        }
    }
}

// ---------------- launcher ----------------
extern "C" void kernel_launch(void* const* d_in, const int* in_sizes, int n_in,
                              void* d_out, int out_size) {
    const float* x      = (const float*)d_in[0];
    const float* noise  = (const float*)d_in[1];
    const float* W1     = (const float*)d_in[2];
    const float* b1     = (const float*)d_in[3];
    const float* W2     = (const float*)d_in[4];
    const float* b2     = (const float*)d_in[5];
    const float* freqs  = (const float*)d_in[6];
    const float* amps   = (const float*)d_in[7];
    const float* phases = (const float*)d_in[8];
    const float* Wo     = (const float*)d_in[9];
    const float* bo     = (const float*)d_in[10];
    float* out          = (float*)d_out;

    // idempotent, capture-safe; called unconditionally (no static guards allowed)
    cudaFuncSetAttribute(gemm_kernel, cudaFuncAttributeMaxDynamicSharedMemorySize,
                         GEMM_SMEM);

    pool_kernel<<<dim3(Dn / 256, 32, Bn), 256>>>(x);
    gate_kernel<<<dim3(Bn, Hn), 128>>>(W1, b1, W2, b2);
    wave_kernel<<<dim3(Sn / 128, Hn), 128>>>(freqs, amps, phases);
    prepB_kernel<<<dim3(32, 32), 256>>>(Wo);
    density_kernel<<<dim3(Sn / 256, Bn, Hn * 2), 256>>>(noise);
    prepA_kernel<<<8192, 256>>>(x);
    gemm_kernel<<<dim3(Dn / 128, (Bn * Sn) / 128), 256, GEMM_SMEM>>>(x, bo, out);
}